// round 14
// baseline (speedup 1.0000x reference)
#include <cuda_runtime.h>
#include <cstdint>
#include <cstddef>

// ---------------------------------------------------------------------------
// BinaryDense: out[N,F] = inputs[N,D] @ w_bin[D,F],  N=2^20, D=F=128
// w_bin = 2*bernoulli(partitionable-threefry(key(seed)), hard_sigmoid(W)) - 1
// fp16 mma.sync m16n8k16 GEMM (f32 accum). Warp grid 4-over-M: each warp
// owns 16 rows x 128 cols -> 1x smem read amplification (B is in registers).
// Bitpacked B signs, XOR-swizzled cp.async A, 2 CTAs/SM, triple-buffered.
// ---------------------------------------------------------------------------

#define PAD        132                      // f32 words per SMEM row
#define TM         64                       // CTA tile rows
#define ABUF_FLTS  (TM * PAD)               // 8448 floats = 33792 B
#define SMEM_TOTAL (3 * ABUF_FLTS * 4)      // 3 A buffers = 101376 B per CTA

// w_bin image, [f][d] row-major, values exactly +1.0f / -1.0f
static __device__ float g_B[16384];

// --------------------------- w_bin precompute ------------------------------
// Partitionable threefry2x32 (modern JAX default):
//   key = (0, seed); ctr = (0, idx); bits = out0 ^ out1
//   u = bitcast((bits>>9)|0x3f800000) - 1
//   w_bin = (u < clip((w+1)*0.5,0,1)) ? +1 : -1    (sign(w) if !is_training)

__device__ __forceinline__ uint32_t rotl32(uint32_t x, int r) {
    return (x << r) | (x >> (32 - r));
}

__global__ void wbin_kernel(const float* __restrict__ w,
                            const int* __restrict__ seedp,
                            const int* __restrict__ trainp) {
    int idx = blockIdx.x * blockDim.x + threadIdx.x;   // (d, f) row-major
    int d = idx >> 7;
    int f = idx & 127;
    float wv = w[idx];
    float bin;
    if (*trainp) {
        uint32_t k0 = 0u, k1 = (uint32_t)(*seedp);
        uint32_t x0 = 0u;                  // counter hi word
        uint32_t x1 = (uint32_t)idx;       // counter lo word
        uint32_t ks[3] = { k0, k1, k0 ^ k1 ^ 0x1BD11BDAu };
        x0 += ks[0];
        x1 += ks[1];
        const int rot[2][4] = { {13, 15, 26, 6}, {17, 29, 16, 24} };
        #pragma unroll
        for (int i = 0; i < 5; i++) {
            #pragma unroll
            for (int j = 0; j < 4; j++) {
                x0 += x1;
                x1 = rotl32(x1, rot[i & 1][j]);
                x1 ^= x0;
            }
            x0 += ks[(i + 1) % 3];
            x1 += ks[(i + 2) % 3] + (uint32_t)(i + 1);
        }
        uint32_t bits = x0 ^ x1;           // partitionable fold
        float u = __uint_as_float((bits >> 9) | 0x3f800000u) - 1.0f;
        float p = fminf(fmaxf((wv + 1.0f) * 0.5f, 0.0f), 1.0f);
        bin = (u < p) ? 1.0f : -1.0f;
    } else {
        bin = (wv > 0.0f) ? 1.0f : -1.0f;
    }
    g_B[f * 128 + d] = bin;   // transposed: [f][d]
}

// ------------------------------- GEMM --------------------------------------

__device__ __forceinline__ uint32_t smem_u32(const void* p) {
    uint32_t a;
    asm("{ .reg .u64 t; cvta.to.shared.u64 t, %1; cvt.u32.u64 %0, t; }"
        : "=r"(a) : "l"(p));
    return a;
}

__device__ __forceinline__ uint32_t f16x2(float hi, float lo) {
    uint32_t d;
    asm("cvt.rn.f16x2.f32 %0, %1, %2;" : "=r"(d) : "f"(hi), "f"(lo));
    return d;
}

// Non-volatile: register deps only; lets the scheduler interleave freely.
__device__ __forceinline__ void mma_f16(float* d, uint32_t a0, uint32_t a1,
                                        uint32_t a2, uint32_t a3,
                                        uint32_t b0, uint32_t b1) {
    asm("mma.sync.aligned.m16n8k16.row.col.f32.f16.f16.f32 "
        "{%0,%1,%2,%3}, {%4,%5,%6,%7}, {%8,%9}, {%0,%1,%2,%3};"
        : "+f"(d[0]), "+f"(d[1]), "+f"(d[2]), "+f"(d[3])
        : "r"(a0), "r"(a1), "r"(a2), "r"(a3), "r"(b0), "r"(b1));
}

// One 64x128-float A tile -> SMEM with per-row XOR chunk swizzle:
// chunk (m, k4) lands at word m*PAD + 4*(k4 ^ ((m&7)<<2)).
__device__ __forceinline__ void issue_a(uint32_t sbase, const float* __restrict__ A,
                                        int tile, int tid) {
    const char* g = (const char*)(A + (size_t)tile * (TM * 128));
    #pragma unroll
    for (int j = 0; j < 16; j++) {
        int id = tid + j * 128;            // 2048 chunks of 16 B
        int m  = id >> 5;
        int k4 = id & 31;
        uint32_t pos  = (uint32_t)(k4 ^ ((m & 7) << 2));
        uint32_t soff = sbase + (uint32_t)m * (PAD * 4u) + pos * 16u;
        asm volatile("cp.async.cg.shared.global [%0], [%1], 16;"
                     :: "r"(soff), "l"(g + (size_t)m * 512 + (size_t)k4 * 16)
                     : "memory");
    }
}

__global__ void __launch_bounds__(128, 2)
gemm_kernel(const float* __restrict__ A, float* __restrict__ out, int n_tiles) {
    extern __shared__ float smem[];
    int tid  = threadIdx.x;
    int wm   = tid >> 5;          // warp 0..3 -> 16-row slab of the tile
    int lane = tid & 31;
    int r    = lane >> 2;         // fragment row group 0..7
    int c    = lane & 3;          // fragment col group 0..3

    float* Ab0 = smem;
    float* Ab1 = smem + ABUF_FLTS;
    float* Ab2 = smem + 2 * ABUF_FLTS;
    uint32_t sbase[3];
    sbase[0] = smem_u32(Ab0);
    sbase[1] = sbase[0] + ABUF_FLTS * 4;
    sbase[2] = sbase[0] + 2 * ABUF_FLTS * 4;

    // ---- pack B signs for fp16 k-pattern, all 16 n-blocks ----
    // bit (4q + jj) of bw[nf] = sign(B^T[nf*8+r][16q + 2c + (jj&1) + 8*((jj>>1)&1)])
    uint32_t bw[16];
    #pragma unroll
    for (int nf = 0; nf < 16; nf++) {
        const float* bp = g_B + (size_t)(nf * 8 + r) * 128;
        uint32_t w = 0;
        #pragma unroll
        for (int j = 0; j < 32; j++) {
            int k = ((j >> 2) << 4) + 2 * c + (j & 1) + (((j >> 1) & 1) << 3);
            w |= (__float_as_uint(bp[k]) >> 31) << j;
        }
        bw[nf] = w;
    }

    int grid  = (int)gridDim.x;
    int tile0 = (int)blockIdx.x;

    // ---- prologue: fill 3 A buffers ----
    issue_a(sbase[0], A, tile0, tid);
    asm volatile("cp.async.commit_group;" ::: "memory");
    if (tile0 + grid < n_tiles) issue_a(sbase[1], A, tile0 + grid, tid);
    asm volatile("cp.async.commit_group;" ::: "memory");
    if (tile0 + 2 * grid < n_tiles) issue_a(sbase[2], A, tile0 + 2 * grid, tid);
    asm volatile("cp.async.commit_group;" ::: "memory");

    // per-thread constant word offset within a row: 4*(c>>1) + 2*(c&1)
    int offc = 4 * (c >> 1) + 2 * (c & 1);

    int it = 0;
    for (int tile = tile0; tile < n_tiles; tile += grid, it++) {
        int b3 = it % 3;
        const float* Ab = (b3 == 0) ? Ab0 : (b3 == 1) ? Ab1 : Ab2;
        uint32_t abase = sbase[b3];

        asm volatile("cp.async.wait_group 2;" ::: "memory");
        __syncthreads();

        float acc[16][4];
        #pragma unroll
        for (int nf = 0; nf < 16; nf++)
            #pragma unroll
            for (int q = 0; q < 4; q++) acc[nf][q] = 0.0f;

        // warp's A rows: wm*16 + r (and +8)
        const float* ap = Ab + (size_t)((wm * 16 + r) * PAD + offc);

        #pragma unroll
        for (int q = 0; q < 8; q++) {                   // k0 = 16q
            // swizzled chunk base for this q: word 16*(q^r) within the row
            const float* aq = ap + 16 * (q ^ r);
            float2 v00 = *(const float2*)(aq);                 // (g,   k..k+1)
            float2 v10 = *(const float2*)(aq + 8 * PAD);       // (g+8, k..k+1)
            float2 v01 = *(const float2*)(aq + 8);             // (g,   k+8..k+9)
            float2 v11 = *(const float2*)(aq + 8 * PAD + 8);   // (g+8, k+8..k+9)
            uint32_t fa0 = f16x2(v00.y, v00.x);
            uint32_t fa1 = f16x2(v10.y, v10.x);
            uint32_t fa2 = f16x2(v01.y, v01.x);
            uint32_t fa3 = f16x2(v11.y, v11.x);

            #pragma unroll
            for (int nf = 0; nf < 16; nf++) {
                uint32_t nib = bw[nf] >> (4 * q);
                uint32_t s0 = 0x3C003C00u | ((nib & 1u) << 15) | ((nib & 2u) << 30);
                uint32_t s1 = 0x3C003C00u | ((nib & 4u) << 13) | ((nib & 8u) << 28);
                mma_f16(acc[nf], fa0, fa1, fa2, fa3, s0, s1);
            }
        }

        __syncthreads();   // all warps done reading this A buffer

        int nt = tile + 3 * grid;
        if (nt < n_tiles) issue_a(abase, A, nt, tid);
        asm volatile("cp.async.commit_group;" ::: "memory");

        // ---- epilogue: streaming stores (warp slab: rows wm*16..+15, all cols) ----
        float* obase = out + (size_t)(tile * TM + wm * 16) * 128;
        #pragma unroll
        for (int nf = 0; nf < 16; nf++) {
            float* p = obase + (size_t)r * 128 + nf * 8 + c * 2;
            __stcs((float2*)p,             make_float2(acc[nf][0], acc[nf][1]));
            __stcs((float2*)(p + 8 * 128), make_float2(acc[nf][2], acc[nf][3]));
        }
    }
}

// ------------------------------ launch -------------------------------------

extern "C" void kernel_launch(void* const* d_in, const int* in_sizes, int n_in,
                              void* d_out, int out_size) {
    const float* A       = (const float*)d_in[0];
    const float* W       = (const float*)d_in[1];
    const int*   seed    = (const int*)d_in[2];
    const int*   istrain = (const int*)d_in[3];
    float* out = (float*)d_out;

    int N = in_sizes[0] / 128;
    int n_tiles = N / TM;                  // 16384

    wbin_kernel<<<64, 256>>>(W, seed, istrain);

    int sms = 148;
    cudaDeviceGetAttribute(&sms, cudaDevAttrMultiProcessorCount, 0);
    int grid = 2 * sms;                    // 2 CTAs per SM
    if (grid > n_tiles) grid = n_tiles;

    cudaFuncSetAttribute(gemm_kernel, cudaFuncAttributeMaxDynamicSharedMemorySize, SMEM_TOTAL);
    gemm_kernel<<<grid, 128, SMEM_TOTAL>>>(A, out, n_tiles);
}

// round 15
// speedup vs baseline: 1.3585x; 1.3585x over previous
#include <cuda_runtime.h>
#include <cstdint>
#include <cstddef>

// ---------------------------------------------------------------------------
// BinaryDense: out[N,F] = inputs[N,D] @ w_bin[D,F],  N=2^20, D=F=128
// w_bin = 2*bernoulli(partitionable-threefry(key(seed)), hard_sigmoid(W)) - 1
// fp16 mma.sync m16n8k16 GEMM (f32 accum). Warp grid 2m x 2n (tile 32x64):
// 2x smem amplification, 64 acc regs, 16 MMA chains -- fits RF, no spill.
// Bitpacked B signs, XOR-swizzled cp.async A, 2 CTAs/SM, triple-buffered.
// ---------------------------------------------------------------------------

#define PAD        132                      // f32 words per SMEM row
#define TM         64                       // CTA tile rows
#define ABUF_FLTS  (TM * PAD)               // 8448 floats = 33792 B
#define SMEM_TOTAL (3 * ABUF_FLTS * 4)      // 3 A buffers = 101376 B per CTA

// w_bin image, [f][d] row-major, values exactly +1.0f / -1.0f
static __device__ float g_B[16384];

// --------------------------- w_bin precompute ------------------------------
// Partitionable threefry2x32 (modern JAX default):
//   key = (0, seed); ctr = (0, idx); bits = out0 ^ out1
//   u = bitcast((bits>>9)|0x3f800000) - 1
//   w_bin = (u < clip((w+1)*0.5,0,1)) ? +1 : -1    (sign(w) if !is_training)

__device__ __forceinline__ uint32_t rotl32(uint32_t x, int r) {
    return (x << r) | (x >> (32 - r));
}

__global__ void wbin_kernel(const float* __restrict__ w,
                            const int* __restrict__ seedp,
                            const int* __restrict__ trainp) {
    int idx = blockIdx.x * blockDim.x + threadIdx.x;   // (d, f) row-major
    int d = idx >> 7;
    int f = idx & 127;
    float wv = w[idx];
    float bin;
    if (*trainp) {
        uint32_t k0 = 0u, k1 = (uint32_t)(*seedp);
        uint32_t x0 = 0u;                  // counter hi word
        uint32_t x1 = (uint32_t)idx;       // counter lo word
        uint32_t ks[3] = { k0, k1, k0 ^ k1 ^ 0x1BD11BDAu };
        x0 += ks[0];
        x1 += ks[1];
        const int rot[2][4] = { {13, 15, 26, 6}, {17, 29, 16, 24} };
        #pragma unroll
        for (int i = 0; i < 5; i++) {
            #pragma unroll
            for (int j = 0; j < 4; j++) {
                x0 += x1;
                x1 = rotl32(x1, rot[i & 1][j]);
                x1 ^= x0;
            }
            x0 += ks[(i + 1) % 3];
            x1 += ks[(i + 2) % 3] + (uint32_t)(i + 1);
        }
        uint32_t bits = x0 ^ x1;           // partitionable fold
        float u = __uint_as_float((bits >> 9) | 0x3f800000u) - 1.0f;
        float p = fminf(fmaxf((wv + 1.0f) * 0.5f, 0.0f), 1.0f);
        bin = (u < p) ? 1.0f : -1.0f;
    } else {
        bin = (wv > 0.0f) ? 1.0f : -1.0f;
    }
    g_B[f * 128 + d] = bin;   // transposed: [f][d]
}

// ------------------------------- GEMM --------------------------------------

__device__ __forceinline__ uint32_t smem_u32(const void* p) {
    uint32_t a;
    asm("{ .reg .u64 t; cvta.to.shared.u64 t, %1; cvt.u32.u64 %0, t; }"
        : "=r"(a) : "l"(p));
    return a;
}

__device__ __forceinline__ uint32_t f16x2(float hi, float lo) {
    uint32_t d;
    asm("cvt.rn.f16x2.f32 %0, %1, %2;" : "=r"(d) : "f"(hi), "f"(lo));
    return d;
}

// Non-volatile: register deps only; lets the scheduler interleave freely.
__device__ __forceinline__ void mma_f16(float* d, uint32_t a0, uint32_t a1,
                                        uint32_t a2, uint32_t a3,
                                        uint32_t b0, uint32_t b1) {
    asm("mma.sync.aligned.m16n8k16.row.col.f32.f16.f16.f32 "
        "{%0,%1,%2,%3}, {%4,%5,%6,%7}, {%8,%9}, {%0,%1,%2,%3};"
        : "+f"(d[0]), "+f"(d[1]), "+f"(d[2]), "+f"(d[3])
        : "r"(a0), "r"(a1), "r"(a2), "r"(a3), "r"(b0), "r"(b1));
}

// One 64x128-float A tile -> SMEM with per-row XOR chunk swizzle:
// chunk (m, k4) lands at word m*PAD + 4*(k4 ^ ((m&7)<<2)).
__device__ __forceinline__ void issue_a(uint32_t sbase, const float* __restrict__ A,
                                        int tile, int tid) {
    const char* g = (const char*)(A + (size_t)tile * (TM * 128));
    #pragma unroll
    for (int j = 0; j < 16; j++) {
        int id = tid + j * 128;            // 2048 chunks of 16 B
        int m  = id >> 5;
        int k4 = id & 31;
        uint32_t pos  = (uint32_t)(k4 ^ ((m & 7) << 2));
        uint32_t soff = sbase + (uint32_t)m * (PAD * 4u) + pos * 16u;
        asm volatile("cp.async.cg.shared.global [%0], [%1], 16;"
                     :: "r"(soff), "l"(g + (size_t)m * 512 + (size_t)k4 * 16)
                     : "memory");
    }
}

__global__ void __launch_bounds__(128, 2)
gemm_kernel(const float* __restrict__ A, float* __restrict__ out, int n_tiles) {
    extern __shared__ float smem[];
    int tid  = threadIdx.x;
    int wid  = tid >> 5;
    int wm   = wid >> 1;          // 0..1 -> 32-row half
    int wn   = wid & 1;           // 0..1 -> 64-col half
    int lane = tid & 31;
    int r    = lane >> 2;         // fragment row group 0..7
    int c    = lane & 3;          // fragment col group 0..3

    float* Ab0 = smem;
    float* Ab1 = smem + ABUF_FLTS;
    float* Ab2 = smem + 2 * ABUF_FLTS;
    uint32_t sbase[3];
    sbase[0] = smem_u32(Ab0);
    sbase[1] = sbase[0] + ABUF_FLTS * 4;
    sbase[2] = sbase[0] + 2 * ABUF_FLTS * 4;

    // ---- pack B signs for fp16 k-pattern, 8 n-blocks ----
    // bit (4q + jj) of bw[nf] = sign(B^T[n][16q + 2c + (jj&1) + 8*((jj>>1)&1)])
    uint32_t bw[8];
    #pragma unroll
    for (int nf = 0; nf < 8; nf++) {
        const float* bp = g_B + (size_t)((wn * 64 + nf * 8 + r)) * 128;
        uint32_t w = 0;
        #pragma unroll
        for (int j = 0; j < 32; j++) {
            int k = ((j >> 2) << 4) + 2 * c + (j & 1) + (((j >> 1) & 1) << 3);
            w |= (__float_as_uint(bp[k]) >> 31) << j;
        }
        bw[nf] = w;
    }

    int grid  = (int)gridDim.x;
    int tile0 = (int)blockIdx.x;

    // ---- prologue: fill 3 A buffers ----
    issue_a(sbase[0], A, tile0, tid);
    asm volatile("cp.async.commit_group;" ::: "memory");
    if (tile0 + grid < n_tiles) issue_a(sbase[1], A, tile0 + grid, tid);
    asm volatile("cp.async.commit_group;" ::: "memory");
    if (tile0 + 2 * grid < n_tiles) issue_a(sbase[2], A, tile0 + 2 * grid, tid);
    asm volatile("cp.async.commit_group;" ::: "memory");

    // per-thread constant word offset within a row: 4*(c>>1) + 2*(c&1)
    int offc = 4 * (c >> 1) + 2 * (c & 1);

    int it = 0;
    for (int tile = tile0; tile < n_tiles; tile += grid, it++) {
        int b3 = it % 3;
        const float* Ab = (b3 == 0) ? Ab0 : (b3 == 1) ? Ab1 : Ab2;
        uint32_t abase = sbase[b3];

        asm volatile("cp.async.wait_group 2;" ::: "memory");
        __syncthreads();

        float acc[2][8][4];
        #pragma unroll
        for (int mf = 0; mf < 2; mf++)
            #pragma unroll
            for (int nf = 0; nf < 8; nf++)
                #pragma unroll
                for (int q = 0; q < 4; q++) acc[mf][nf][q] = 0.0f;

        // warp's A rows: wm*32 + mf*16 + r (and +8)
        const float* ap = Ab + (size_t)((wm * 32 + r) * PAD + offc);

        #pragma unroll
        for (int q = 0; q < 8; q++) {                   // k0 = 16q
            // swizzled chunk base for this q: word 16*(q^r) within the row
            const float* aq = ap + 16 * (q ^ r);
            uint32_t fa[2][4];
            #pragma unroll
            for (int mf = 0; mf < 2; mf++) {
                const float* am = aq + (size_t)(mf * 16) * PAD;
                float2 v00 = *(const float2*)(am);                 // (g,   k..k+1)
                float2 v10 = *(const float2*)(am + 8 * PAD);       // (g+8, k..k+1)
                float2 v01 = *(const float2*)(am + 8);             // (g,   k+8..k+9)
                float2 v11 = *(const float2*)(am + 8 * PAD + 8);   // (g+8, k+8..k+9)
                fa[mf][0] = f16x2(v00.y, v00.x);
                fa[mf][1] = f16x2(v10.y, v10.x);
                fa[mf][2] = f16x2(v01.y, v01.x);
                fa[mf][3] = f16x2(v11.y, v11.x);
            }
            #pragma unroll
            for (int nf = 0; nf < 8; nf++) {
                uint32_t nib = bw[nf] >> (4 * q);
                uint32_t s0 = 0x3C003C00u | ((nib & 1u) << 15) | ((nib & 2u) << 30);
                uint32_t s1 = 0x3C003C00u | ((nib & 4u) << 13) | ((nib & 8u) << 28);
                mma_f16(acc[0][nf], fa[0][0], fa[0][1], fa[0][2], fa[0][3], s0, s1);
                mma_f16(acc[1][nf], fa[1][0], fa[1][1], fa[1][2], fa[1][3], s0, s1);
            }
        }

        __syncthreads();   // all warps done reading this A buffer

        int nt = tile + 3 * grid;
        if (nt < n_tiles) issue_a(abase, A, nt, tid);
        asm volatile("cp.async.commit_group;" ::: "memory");

        // ---- epilogue: streaming stores (warp slab: rows wm*32..+31, cols wn*64..+63) ----
        float* obase = out + (size_t)(tile * TM + wm * 32) * 128 + wn * 64;
        #pragma unroll
        for (int mf = 0; mf < 2; mf++) {
            #pragma unroll
            for (int nf = 0; nf < 8; nf++) {
                float* p = obase + (size_t)(mf * 16 + r) * 128 + nf * 8 + c * 2;
                __stcs((float2*)p,             make_float2(acc[mf][nf][0], acc[mf][nf][1]));
                __stcs((float2*)(p + 8 * 128), make_float2(acc[mf][nf][2], acc[mf][nf][3]));
            }
        }
    }
}

// ------------------------------ launch -------------------------------------

extern "C" void kernel_launch(void* const* d_in, const int* in_sizes, int n_in,
                              void* d_out, int out_size) {
    const float* A       = (const float*)d_in[0];
    const float* W       = (const float*)d_in[1];
    const int*   seed    = (const int*)d_in[2];
    const int*   istrain = (const int*)d_in[3];
    float* out = (float*)d_out;

    int N = in_sizes[0] / 128;
    int n_tiles = N / TM;                  // 16384

    wbin_kernel<<<64, 256>>>(W, seed, istrain);

    int sms = 148;
    cudaDeviceGetAttribute(&sms, cudaDevAttrMultiProcessorCount, 0);
    int grid = 2 * sms;                    // 2 CTAs per SM
    if (grid > n_tiles) grid = n_tiles;

    cudaFuncSetAttribute(gemm_kernel, cudaFuncAttributeMaxDynamicSharedMemorySize, SMEM_TOTAL);
    gemm_kernel<<<grid, 128, SMEM_TOTAL>>>(A, out, n_tiles);
}